// round 7
// baseline (speedup 1.0000x reference)
#include <cuda_runtime.h>

// VectorQuantizer: z [32768, 64] fp32, codebook [1024, 64] fp32.
// Outputs (float32, concatenated): z_q (2097152) | loss (1) | indices (32768).
//
// d2_k = fl( fl(znorm + cnorm_k) - fl(2 * dot_k) )  -- replicates reference
// rounding composition so argmin matches jnp.argmin (first-min tie-break).
// Per-lane arithmetic sequence identical to the 146us passing kernel.

#define NROWS    32768
#define DIM      64
#define KCODES   1024
#define TM       64          // rows per block
#define TN       64          // codes per tile
#define NTILES   (KCODES / TN)
#define NTHREADS 256
#define NBLOCKS  (NROWS / TM)
#define ZS       68          // float stride, 68*4B = 272B = 17x16B (keeps 16B align)
#define CSD      66          // float2 stride, 66*8B = 528B = 33x16B

#define ZS_BYTES   (DIM * ZS * 4)          // 17408
#define CSD_BYTES  (DIM * CSD * 8)         // 33792
#define SMEM_BYTES (ZS_BYTES + CSD_BYTES + TM*4 + TM*4 + 16*4)  // 51776

typedef unsigned long long ull;

__device__ __align__(16) float g_cnorm[KCODES];
__device__ float g_partials[NBLOCKS];

__device__ __forceinline__ void fma2(ull& acc, ull a, ull b) {
    asm("fma.rn.f32x2 %0, %1, %2, %0;" : "+l"(acc) : "l"(a), "l"(b));
}
__device__ __forceinline__ void unpack2(ull v, float& lo, float& hi) {
    asm("mov.b64 {%0, %1}, %2;" : "=f"(lo), "=f"(hi) : "l"(v));
}

// ---------------------------------------------------------------------------
// Kernel 1: codebook row norms. MLP-16 float4 loads, then sequential fp32
// adds in ascending element order (same rounding as square-then-sum ref).
// ---------------------------------------------------------------------------
__global__ void cnorm_kernel(const float* __restrict__ cb) {
    int k = blockIdx.x * 64 + threadIdx.x;
    const float4* row = (const float4*)(cb + k * DIM);
    float4 v[16];
#pragma unroll
    for (int i = 0; i < 16; i++) v[i] = __ldg(row + i);
    float s = 0.0f;
#pragma unroll
    for (int i = 0; i < 16; i++) {
        s = __fadd_rn(s, __fmul_rn(v[i].x, v[i].x));
        s = __fadd_rn(s, __fmul_rn(v[i].y, v[i].y));
        s = __fadd_rn(s, __fmul_rn(v[i].z, v[i].z));
        s = __fadd_rn(s, __fmul_rn(v[i].w, v[i].w));
    }
    g_cnorm[k] = s;
}

// ---------------------------------------------------------------------------
// Kernel 2: main VQ. Each block: 64 rows x 1024 codes (16 tiles of 64).
// Thread (tx, ty): rows ty*4..+3, codes tile*64 + tx*4..+3.
// z transposed in smem (row-quads contiguous -> native f32x2 row pairs);
// codebook tile stored DUPLICATED as float2{c,c} -> no packs in the loop.
// Inner loop per k: 1 LDS.128 (z, warp-broadcast) + 2 LDS.128 (c) + 8 FFMA2.
// ---------------------------------------------------------------------------
__global__ __launch_bounds__(NTHREADS, 4)
void vq_kernel(const float* __restrict__ z,
               const float* __restrict__ codebook,
               float* __restrict__ out) {
    extern __shared__ char smem_raw[];
    float*  zsT     = (float*)smem_raw;                            // [DIM][ZS]
    float2* csD     = (float2*)(smem_raw + ZS_BYTES);              // [DIM][CSD]
    float*  znorm_s = (float*)(smem_raw + ZS_BYTES + CSD_BYTES);   // [TM]
    int*    ridx_s  = (int*)(znorm_s + TM);                        // [TM]
    float*  lsum_s  = (float*)(ridx_s + TM);                       // [16]

    const int tid = threadIdx.x;
    const int tx = tid & 15;            // code group
    const int ty = tid >> 4;            // row group
    const int rowBase = blockIdx.x * TM;

    // ---- load z tile (LDG.128 coalesced), store transposed ----
    {
        const float4* zsrc = (const float4*)(z + rowBase * DIM);
#pragma unroll
        for (int i = 0; i < 4; i++) {
            int flat4 = i * NTHREADS + tid;          // over 64 rows x 16 quads
            int r = flat4 >> 4, q = flat4 & 15;
            float4 v = zsrc[flat4];
            zsT[(q * 4 + 0) * ZS + r] = v.x;
            zsT[(q * 4 + 1) * ZS + r] = v.y;
            zsT[(q * 4 + 2) * ZS + r] = v.z;
            zsT[(q * 4 + 3) * ZS + r] = v.w;
        }
    }
    __syncthreads();

    // ---- row norms: square (rounded) then sequential add, ascending d ----
    if (tid < TM) {
        float s = 0.0f;
#pragma unroll
        for (int d = 0; d < DIM; d++) {
            float v = zsT[d * ZS + tid];
            s = __fadd_rn(s, __fmul_rn(v, v));
        }
        znorm_s[tid] = s;
    }
    __syncthreads();

    float zn[4];
#pragma unroll
    for (int r = 0; r < 4; r++) zn[r] = znorm_s[(ty << 2) + r];

    float minval[4] = {3.4e38f, 3.4e38f, 3.4e38f, 3.4e38f};
    int   minidx[4] = {0, 0, 0, 0};

    for (int t = 0; t < NTILES; t++) {
        const int cbase = t * TN;

        // ---- load code tile (LDG.128), store transposed + duplicated ----
        {
            const float4* csrc = (const float4*)(codebook + cbase * DIM);
#pragma unroll
            for (int i = 0; i < 4; i++) {
                int flat4 = i * NTHREADS + tid;      // over 64 codes x 16 quads
                int cl = flat4 >> 4, q = flat4 & 15;
                float4 v = __ldg(csrc + flat4);
                csD[(q * 4 + 0) * CSD + cl] = make_float2(v.x, v.x);
                csD[(q * 4 + 1) * CSD + cl] = make_float2(v.y, v.y);
                csD[(q * 4 + 2) * CSD + cl] = make_float2(v.z, v.z);
                csD[(q * 4 + 3) * CSD + cl] = make_float2(v.w, v.w);
            }
        }
        __syncthreads();

        // acc[rp][c]: rp=0 -> rows (r0,r1) packed, rp=1 -> rows (r2,r3)
        ull acc[2][4];
#pragma unroll
        for (int c = 0; c < 4; c++) { acc[0][c] = 0ull; acc[1][c] = 0ull; }

#pragma unroll 16
        for (int k = 0; k < DIM; k++) {
            const ull* zp = (const ull*)(zsT + k * ZS + (ty << 2));
            ull z01 = zp[0];           // {z[r0], z[r1]}  native pair
            ull z23 = zp[1];           // {z[r2], z[r3]}
            const ull* cp = (const ull*)(csD + k * CSD + (tx << 2));
            ull c0 = cp[0];            // {c0, c0}  pre-duplicated
            ull c1 = cp[1];
            ull c2 = cp[2];
            ull c3 = cp[3];
            fma2(acc[0][0], z01, c0); fma2(acc[1][0], z23, c0);
            fma2(acc[0][1], z01, c1); fma2(acc[1][1], z23, c1);
            fma2(acc[0][2], z01, c2); fma2(acc[1][2], z23, c2);
            fma2(acc[0][3], z01, c3); fma2(acc[1][3], z23, c3);
        }

        // epilogue: dist = fl( fl(znorm + cnorm) - fl(2*dot) ), codes ascending
        float4 cn4 = *(const float4*)(g_cnorm + cbase + (tx << 2));
        float cna[4] = {cn4.x, cn4.y, cn4.z, cn4.w};
#pragma unroll
        for (int c = 0; c < 4; c++) {
            int code = cbase + (tx << 2) + c;
#pragma unroll
            for (int rp = 0; rp < 2; rp++) {
                float dlo, dhi;
                unpack2(acc[rp][c], dlo, dhi);
                int r0 = rp * 2, r1 = rp * 2 + 1;
                float d0 = __fsub_rn(__fadd_rn(zn[r0], cna[c]), __fmul_rn(2.0f, dlo));
                if (d0 < minval[r0]) { minval[r0] = d0; minidx[r0] = code; }
                float d1 = __fsub_rn(__fadd_rn(zn[r1], cna[c]), __fmul_rn(2.0f, dhi));
                if (d1 < minval[r1]) { minval[r1] = d1; minidx[r1] = code; }
            }
        }
        __syncthreads();
    }

    // ---- cross-lane reduction over the 16 code-lanes (same ty group) ----
#pragma unroll
    for (int r = 0; r < 4; r++) {
#pragma unroll
        for (int m = 8; m >= 1; m >>= 1) {
            float ov = __shfl_xor_sync(0xffffffffu, minval[r], m);
            int   oi = __shfl_xor_sync(0xffffffffu, minidx[r], m);
            if (ov < minval[r] || (ov == minval[r] && oi < minidx[r])) {
                minval[r] = ov; minidx[r] = oi;
            }
        }
    }

    if (tx == 0) {
        float s = 0.0f;
#pragma unroll
        for (int r = 0; r < 4; r++) {
            ridx_s[(ty << 2) + r] = minidx[r];
            s = __fadd_rn(s, minval[r]);   // = ||z_r - c_idx||^2
        }
        lsum_s[ty] = s;
    }
    __syncthreads();

    if (tid == 0) {
        float s = 0.0f;
#pragma unroll
        for (int i = 0; i < 16; i++) s = __fadd_rn(s, lsum_s[i]);
        g_partials[blockIdx.x] = s;
    }

    // ---- write indices (as float) ----
    if (tid < TM) {
        out[NROWS * DIM + 1 + rowBase + tid] = (float)ridx_s[tid];
    }

    // ---- write z_q = codebook[idx] (coalesced, L2-hot gather) ----
#pragma unroll
    for (int i = 0; i < 16; i++) {
        int flat = i * NTHREADS + tid;
        int r = flat >> 6, c = flat & 63;
        out[(rowBase + r) * DIM + c] = codebook[ridx_s[r] * DIM + c];
    }
}

// ---------------------------------------------------------------------------
// Kernel 3: deterministic loss reduce.
// loss = mean + 0.25*mean, mean = sum(||z - z_q||^2) / (N*D)
// ---------------------------------------------------------------------------
__global__ void loss_kernel(float* __restrict__ out) {
    __shared__ float s[NBLOCKS];
    int tid = threadIdx.x;
    s[tid] = g_partials[tid];
    __syncthreads();
    for (int m = NBLOCKS / 2; m > 0; m >>= 1) {
        if (tid < m) s[tid] = __fadd_rn(s[tid], s[tid + m]);
        __syncthreads();
    }
    if (tid == 0) {
        float mean = s[0] / (float)(NROWS * DIM);   // /2^21: exact
        out[NROWS * DIM] = __fadd_rn(mean, __fmul_rn(0.25f, mean));
    }
}

extern "C" void kernel_launch(void* const* d_in, const int* in_sizes, int n_in,
                              void* d_out, int out_size) {
    const float* z        = (const float*)d_in[0];
    const float* codebook = (const float*)d_in[1];
    float* out = (float*)d_out;

    static int attr_done = 0;
    if (!attr_done) {
        cudaFuncSetAttribute(vq_kernel,
                             cudaFuncAttributeMaxDynamicSharedMemorySize,
                             SMEM_BYTES);
        attr_done = 1;
    }

    cnorm_kernel<<<KCODES / 64, 64>>>(codebook);
    vq_kernel<<<NBLOCKS, NTHREADS, SMEM_BYTES>>>(z, codebook, out);
    loss_kernel<<<1, NBLOCKS>>>(out);
}

// round 9
// speedup vs baseline: 1.9914x; 1.9914x over previous
#include <cuda_runtime.h>

// VectorQuantizer: z [32768, 64] fp32, codebook [1024, 64] fp32.
// Outputs (float32, concatenated): z_q (2097152) | loss (1) | indices (32768).
//
// d2_k = fl( fl(znorm + cnorm_k) - fl(2 * dot_k) )  -- replicates reference
// rounding composition so argmin matches jnp.argmin (first-min tie-break).
// Per-(row,code) arithmetic sequence identical to the 146us passing kernel.

#define NROWS    32768
#define DIM      64
#define KCODES   1024
#define TM       64          // rows per block
#define TN       64          // codes per tile
#define NTILES   (KCODES / TN)
#define NTHREADS 256
#define NBLOCKS  (NROWS / TM)
#define ZSD      66          // float2 stride: 528B row, 16B-aligned
#define CS       68          // float stride: 272B row, 16B-aligned

#define ZSD_BYTES (DIM * ZSD * 8)            // 33792
#define CS_BYTES  (DIM * CS * 4)             // 17408
#define SMEM_BYTES (ZSD_BYTES + CS_BYTES + TM*4 + TM*4 + 16*4)  // 51776

typedef unsigned long long ull;

__device__ __align__(16) float g_cnorm[KCODES];
__device__ float g_partials[NBLOCKS];

__device__ __forceinline__ void fma2(ull& acc, ull a, ull b) {
    asm("fma.rn.f32x2 %0, %1, %2, %0;" : "+l"(acc) : "l"(a), "l"(b));
}
__device__ __forceinline__ void unpack2(ull v, float& lo, float& hi) {
    asm("mov.b64 {%0, %1}, %2;" : "=f"(lo), "=f"(hi) : "l"(v));
}

// ---------------------------------------------------------------------------
// Kernel 1: codebook row norms (verified 5.3us version). MLP-16 float4 loads,
// sequential fp32 adds ascending -- same rounding as square-then-sum ref.
// ---------------------------------------------------------------------------
__global__ void cnorm_kernel(const float* __restrict__ cb) {
    int k = blockIdx.x * 64 + threadIdx.x;
    const float4* row = (const float4*)(cb + k * DIM);
    float4 v[16];
#pragma unroll
    for (int i = 0; i < 16; i++) v[i] = __ldg(row + i);
    float s = 0.0f;
#pragma unroll
    for (int i = 0; i < 16; i++) {
        s = __fadd_rn(s, __fmul_rn(v[i].x, v[i].x));
        s = __fadd_rn(s, __fmul_rn(v[i].y, v[i].y));
        s = __fadd_rn(s, __fmul_rn(v[i].z, v[i].z));
        s = __fadd_rn(s, __fmul_rn(v[i].w, v[i].w));
    }
    g_cnorm[k] = s;
}

// ---------------------------------------------------------------------------
// Kernel 2: main VQ. Block = 64 rows x 1024 codes (16 tiles of 64).
// Thread (tx, ty): rows ty*4..+3, codes tile*64 + tx*4..+3.
// z stored transposed + duplicated as float2{z,z} (2 distinct/warp -> N=1
// broadcast reads); codebook tile transposed, read as contiguous float4
// (conflict-free). Inner loop: 2 LDS.128(z) + 1 LDS.128(c) + 8 FFMA2, 0 MOVs.
// Accumulators pack CODE pairs: acc[r][cp] = {dot(r,c2cp), dot(r,c2cp+1)}.
// ---------------------------------------------------------------------------
__global__ __launch_bounds__(NTHREADS, 4)
void vq_kernel(const float* __restrict__ z,
               const float* __restrict__ codebook,
               float* __restrict__ out) {
    extern __shared__ char smem_raw[];
    float2* zsD     = (float2*)smem_raw;                           // [DIM][ZSD]
    float*  csT     = (float*)(smem_raw + ZSD_BYTES);              // [DIM][CS]
    float*  znorm_s = (float*)(smem_raw + ZSD_BYTES + CS_BYTES);   // [TM]
    int*    ridx_s  = (int*)(znorm_s + TM);                        // [TM]
    float*  lsum_s  = (float*)(ridx_s + TM);                       // [16]

    const int tid = threadIdx.x;
    const int tx = tid & 15;            // code group
    const int ty = tid >> 4;            // row group
    const int rowBase = blockIdx.x * TM;

    // ---- load z tile (LDG.128 coalesced), store transposed + duplicated ----
    {
        const float4* zsrc = (const float4*)(z + rowBase * DIM);
#pragma unroll
        for (int i = 0; i < 4; i++) {
            int flat4 = i * NTHREADS + tid;          // 64 rows x 16 quads
            int r = flat4 >> 4, q = flat4 & 15;
            float4 v = zsrc[flat4];
            zsD[(q * 4 + 0) * ZSD + r] = make_float2(v.x, v.x);
            zsD[(q * 4 + 1) * ZSD + r] = make_float2(v.y, v.y);
            zsD[(q * 4 + 2) * ZSD + r] = make_float2(v.z, v.z);
            zsD[(q * 4 + 3) * ZSD + r] = make_float2(v.w, v.w);
        }
    }
    __syncthreads();

    // ---- row norms: square (rounded) then sequential add, ascending d ----
    if (tid < TM) {
        float s = 0.0f;
#pragma unroll
        for (int d = 0; d < DIM; d++) {
            float v = zsD[d * ZSD + tid].x;
            s = __fadd_rn(s, __fmul_rn(v, v));
        }
        znorm_s[tid] = s;
    }
    __syncthreads();

    float zn[4];
#pragma unroll
    for (int r = 0; r < 4; r++) zn[r] = znorm_s[(ty << 2) + r];

    float minval[4] = {3.4e38f, 3.4e38f, 3.4e38f, 3.4e38f};
    int   minidx[4] = {0, 0, 0, 0};

    for (int t = 0; t < NTILES; t++) {
        const int cbase = t * TN;

        // ---- load code tile (LDG.128), store transposed (R4 pattern) ----
        {
            const float4* csrc = (const float4*)(codebook + cbase * DIM);
#pragma unroll
            for (int i = 0; i < 4; i++) {
                int flat4 = i * NTHREADS + tid;      // 64 codes x 16 quads
                int cl = flat4 >> 4, q = flat4 & 15;
                float4 v = __ldg(csrc + flat4);
                csT[(q * 4 + 0) * CS + cl] = v.x;
                csT[(q * 4 + 1) * CS + cl] = v.y;
                csT[(q * 4 + 2) * CS + cl] = v.z;
                csT[(q * 4 + 3) * CS + cl] = v.w;
            }
        }
        __syncthreads();

        // acc[r][cp]: row r, code pair cp -> {dot(r,c0),dot(r,c1)} etc.
        ull acc[4][2];
#pragma unroll
        for (int r = 0; r < 4; r++) { acc[r][0] = 0ull; acc[r][1] = 0ull; }

#pragma unroll 8
        for (int k = 0; k < DIM; k++) {
            // z duplicated pairs: 2x LDS.128, broadcast within warp
            const float4* zp4 = (const float4*)(zsD + k * ZSD + (ty << 2));
            float4 za = zp4[0];        // {z0,z0,z1,z1}
            float4 zb = zp4[1];        // {z2,z2,z3,z3}
            ull zd0 = ((const ull*)&za)[0];
            ull zd1 = ((const ull*)&za)[1];
            ull zd2 = ((const ull*)&zb)[0];
            ull zd3 = ((const ull*)&zb)[1];
            // codes: native pairs from contiguous float4 (conflict-free)
            float4 cv = *(const float4*)(csT + k * CS + (tx << 2));
            ull c01 = ((const ull*)&cv)[0];   // {c0, c1}
            ull c23 = ((const ull*)&cv)[1];   // {c2, c3}
            fma2(acc[0][0], zd0, c01); fma2(acc[0][1], zd0, c23);
            fma2(acc[1][0], zd1, c01); fma2(acc[1][1], zd1, c23);
            fma2(acc[2][0], zd2, c01); fma2(acc[2][1], zd2, c23);
            fma2(acc[3][0], zd3, c01); fma2(acc[3][1], zd3, c23);
        }

        // epilogue: d2 = fl( fl(znorm+cnorm) - fl(2*dot) ), codes ascending
        float4 cn4 = *(const float4*)(g_cnorm + cbase + (tx << 2));
        float cna[4] = {cn4.x, cn4.y, cn4.z, cn4.w};
#pragma unroll
        for (int cp = 0; cp < 2; cp++) {
            int code0 = cbase + (tx << 2) + cp * 2;
            float cnl = cna[cp * 2], cnh = cna[cp * 2 + 1];
#pragma unroll
            for (int r = 0; r < 4; r++) {
                float dlo, dhi;
                unpack2(acc[r][cp], dlo, dhi);
                float d0 = __fsub_rn(__fadd_rn(zn[r], cnl), __fmul_rn(2.0f, dlo));
                if (d0 < minval[r]) { minval[r] = d0; minidx[r] = code0; }
                float d1 = __fsub_rn(__fadd_rn(zn[r], cnh), __fmul_rn(2.0f, dhi));
                if (d1 < minval[r]) { minval[r] = d1; minidx[r] = code0 + 1; }
            }
        }
        __syncthreads();
    }

    // ---- cross-lane reduction over the 16 code-lanes (same ty group) ----
#pragma unroll
    for (int r = 0; r < 4; r++) {
#pragma unroll
        for (int m = 8; m >= 1; m >>= 1) {
            float ov = __shfl_xor_sync(0xffffffffu, minval[r], m);
            int   oi = __shfl_xor_sync(0xffffffffu, minidx[r], m);
            if (ov < minval[r] || (ov == minval[r] && oi < minidx[r])) {
                minval[r] = ov; minidx[r] = oi;
            }
        }
    }

    if (tx == 0) {
        float s = 0.0f;
#pragma unroll
        for (int r = 0; r < 4; r++) {
            ridx_s[(ty << 2) + r] = minidx[r];
            s = __fadd_rn(s, minval[r]);   // = ||z_r - c_idx||^2
        }
        lsum_s[ty] = s;
    }
    __syncthreads();

    if (tid == 0) {
        float s = 0.0f;
#pragma unroll
        for (int i = 0; i < 16; i++) s = __fadd_rn(s, lsum_s[i]);
        g_partials[blockIdx.x] = s;
    }

    // ---- write indices (as float) ----
    if (tid < TM) {
        out[NROWS * DIM + 1 + rowBase + tid] = (float)ridx_s[tid];
    }

    // ---- write z_q = codebook[idx] (coalesced, L2-hot gather) ----
#pragma unroll
    for (int i = 0; i < 16; i++) {
        int flat = i * NTHREADS + tid;
        int r = flat >> 6, c = flat & 63;
        out[(rowBase + r) * DIM + c] = codebook[ridx_s[r] * DIM + c];
    }
}

// ---------------------------------------------------------------------------
// Kernel 3: deterministic loss reduce.
// loss = mean + 0.25*mean, mean = sum(||z - z_q||^2) / (N*D)
// ---------------------------------------------------------------------------
__global__ void loss_kernel(float* __restrict__ out) {
    __shared__ float s[NBLOCKS];
    int tid = threadIdx.x;
    s[tid] = g_partials[tid];
    __syncthreads();
    for (int m = NBLOCKS / 2; m > 0; m >>= 1) {
        if (tid < m) s[tid] = __fadd_rn(s[tid], s[tid + m]);
        __syncthreads();
    }
    if (tid == 0) {
        float mean = s[0] / (float)(NROWS * DIM);   // /2^21: exact
        out[NROWS * DIM] = __fadd_rn(mean, __fmul_rn(0.25f, mean));
    }
}

extern "C" void kernel_launch(void* const* d_in, const int* in_sizes, int n_in,
                              void* d_out, int out_size) {
    const float* z        = (const float*)d_in[0];
    const float* codebook = (const float*)d_in[1];
    float* out = (float*)d_out;

    static int attr_done = 0;
    if (!attr_done) {
        cudaFuncSetAttribute(vq_kernel,
                             cudaFuncAttributeMaxDynamicSharedMemorySize,
                             SMEM_BYTES);
        attr_done = 1;
    }

    cnorm_kernel<<<KCODES / 64, 64>>>(codebook);
    vq_kernel<<<NBLOCKS, NTHREADS, SMEM_BYTES>>>(z, codebook, out);
    loss_kernel<<<1, NBLOCKS>>>(out);
}

// round 11
// speedup vs baseline: 2.6975x; 1.3546x over previous
#include <cuda_runtime.h>

// VectorQuantizer: z [32768, 64] fp32, codebook [1024, 64] fp32.
// Outputs (float32, concatenated): z_q (2097152) | loss (1) | indices (32768).
//
// d2_k = fl( fl(znorm + cnorm_k) - fl(2 * dot_k) )  -- replicates reference
// rounding composition so argmin matches jnp.argmin (first-min tie-break).
//
// vq_kernel is the exact 146us R4 form (do not restructure: R5/R6/R9 variants
// all regressed). Only cnorm_kernel is the verified fast version.
// R10 failed with "system not yet initialized" (harness init, infra transient)
// -- resubmitting unchanged.

#define NROWS    32768
#define DIM      64
#define KCODES   1024
#define TM       64          // rows per block
#define TN       64          // codes per tile
#define NTILES   (KCODES / TN)
#define NTHREADS 256
#define NBLOCKS  (NROWS / TM)
#define ZS       68          // smem stride (floats), mult of 4 for float4 align
#define CS       68

typedef unsigned long long ull;

__device__ __align__(16) float g_cnorm[KCODES];
__device__ float g_partials[NBLOCKS];

__device__ __forceinline__ ull pack2dup(float x) {
    ull r; asm("mov.b64 %0, {%1, %1};" : "=l"(r) : "f"(x)); return r;
}
__device__ __forceinline__ void fma2(ull& acc, ull a, ull b) {
    asm("fma.rn.f32x2 %0, %1, %2, %0;" : "+l"(acc) : "l"(a), "l"(b));
}
__device__ __forceinline__ void unpack2(ull v, float& lo, float& hi) {
    asm("mov.b64 {%0, %1}, %2;" : "=f"(lo), "=f"(hi) : "l"(v));
}

// ---------------------------------------------------------------------------
// Kernel 1: codebook row norms (verified fast version: MLP-16 float4 loads,
// sequential fp32 adds in ascending element order -- same rounding as the
// square-then-sum reference).
// ---------------------------------------------------------------------------
__global__ void cnorm_kernel(const float* __restrict__ cb) {
    int k = blockIdx.x * 64 + threadIdx.x;
    const float4* row = (const float4*)(cb + k * DIM);
    float4 v[16];
#pragma unroll
    for (int i = 0; i < 16; i++) v[i] = __ldg(row + i);
    float s = 0.0f;
#pragma unroll
    for (int i = 0; i < 16; i++) {
        s = __fadd_rn(s, __fmul_rn(v[i].x, v[i].x));
        s = __fadd_rn(s, __fmul_rn(v[i].y, v[i].y));
        s = __fadd_rn(s, __fmul_rn(v[i].z, v[i].z));
        s = __fadd_rn(s, __fmul_rn(v[i].w, v[i].w));
    }
    g_cnorm[k] = s;
}

// ---------------------------------------------------------------------------
// Kernel 2: main VQ (exact 146us form). Each block: 64 rows x 1024 codes.
// Thread (tx, ty): rows ty*4..ty*4+3, codes {tile*64 + tx*4 + 0..3}.
// f32x2 packed FMA: z row-pairs are native (contiguous in transposed smem);
// c values duplicated into both halves via pack2dup.
// ---------------------------------------------------------------------------
__global__ __launch_bounds__(NTHREADS, 4)
void vq_kernel(const float* __restrict__ z,
               const float* __restrict__ codebook,
               float* __restrict__ out) {
    __shared__ float zsT[DIM * ZS];     // zsT[d][r]
    __shared__ float csT[DIM * CS];     // csT[d][c_local]
    __shared__ float znorm_s[TM];
    __shared__ int   ridx_s[TM];
    __shared__ float lsum_s[16];

    const int tid = threadIdx.x;
    const int tx = tid & 15;            // code group
    const int ty = tid >> 4;            // row group
    const int rowBase = blockIdx.x * TM;

    // ---- load z tile (coalesced), store transposed ----
    #pragma unroll
    for (int i = 0; i < 16; i++) {
        int flat = i * NTHREADS + tid;
        int r = flat >> 6, d = flat & 63;
        zsT[d * ZS + r] = z[(rowBase + r) * DIM + d];
    }
    __syncthreads();

    // ---- row norms: square (rounded) then sequential add ----
    if (tid < TM) {
        float s = 0.0f;
        #pragma unroll
        for (int k = 0; k < DIM; k++) {
            float v = zsT[k * ZS + tid];
            s = __fadd_rn(s, __fmul_rn(v, v));
        }
        znorm_s[tid] = s;
    }
    __syncthreads();

    float zn[4];
    #pragma unroll
    for (int r = 0; r < 4; r++) zn[r] = znorm_s[(ty << 2) + r];

    float minval[4] = {3.4e38f, 3.4e38f, 3.4e38f, 3.4e38f};
    int   minidx[4] = {0, 0, 0, 0};

    for (int t = 0; t < NTILES; t++) {
        const int cbase = t * TN;

        // load code tile transposed (coalesced global reads)
        #pragma unroll
        for (int i = 0; i < 16; i++) {
            int flat = i * NTHREADS + tid;
            int cl = flat >> 6, d = flat & 63;
            csT[d * CS + cl] = codebook[(cbase + cl) * DIM + d];
        }
        __syncthreads();

        // acc[rp][c]: rp=0 -> rows (0,1) packed, rp=1 -> rows (2,3) packed
        ull acc[2][4];
        #pragma unroll
        for (int rp = 0; rp < 2; rp++)
            #pragma unroll
            for (int c = 0; c < 4; c++) acc[rp][c] = 0ull;  // {0.f, 0.f}

        #pragma unroll 8
        for (int k = 0; k < DIM; k++) {
            const ull* zp = (const ull*)&zsT[k * ZS + (ty << 2)];
            ull z01 = zp[0];           // {z[row0], z[row1]}
            ull z23 = zp[1];           // {z[row2], z[row3]}
            float4 cv = *(const float4*)&csT[k * CS + (tx << 2)];
            ull c0 = pack2dup(cv.x);
            ull c1 = pack2dup(cv.y);
            ull c2 = pack2dup(cv.z);
            ull c3 = pack2dup(cv.w);
            fma2(acc[0][0], z01, c0); fma2(acc[1][0], z23, c0);
            fma2(acc[0][1], z01, c1); fma2(acc[1][1], z23, c1);
            fma2(acc[0][2], z01, c2); fma2(acc[1][2], z23, c2);
            fma2(acc[0][3], z01, c3); fma2(acc[1][3], z23, c3);
        }

        // epilogue: dist = fl( fl(znorm + cnorm) - fl(2*dot) )
        float4 cn4 = *(const float4*)(g_cnorm + cbase + (tx << 2));
        float cna[4] = {cn4.x, cn4.y, cn4.z, cn4.w};
        #pragma unroll
        for (int c = 0; c < 4; c++) {
            int code = cbase + (tx << 2) + c;
            #pragma unroll
            for (int rp = 0; rp < 2; rp++) {
                float dlo, dhi;
                unpack2(acc[rp][c], dlo, dhi);
                int r0 = rp * 2, r1 = rp * 2 + 1;
                float t0 = __fadd_rn(zn[r0], cna[c]);
                float d0 = __fsub_rn(t0, __fmul_rn(2.0f, dlo));
                if (d0 < minval[r0]) { minval[r0] = d0; minidx[r0] = code; }
                float t1 = __fadd_rn(zn[r1], cna[c]);
                float d1 = __fsub_rn(t1, __fmul_rn(2.0f, dhi));
                if (d1 < minval[r1]) { minval[r1] = d1; minidx[r1] = code; }
            }
        }
        __syncthreads();
    }

    // ---- cross-lane reduction over the 16 code-lanes (same ty group) ----
    #pragma unroll
    for (int r = 0; r < 4; r++) {
        #pragma unroll
        for (int m = 8; m >= 1; m >>= 1) {
            float ov = __shfl_xor_sync(0xffffffffu, minval[r], m);
            int   oi = __shfl_xor_sync(0xffffffffu, minidx[r], m);
            if (ov < minval[r] || (ov == minval[r] && oi < minidx[r])) {
                minval[r] = ov; minidx[r] = oi;
            }
        }
    }

    if (tx == 0) {
        float s = 0.0f;
        #pragma unroll
        for (int r = 0; r < 4; r++) {
            ridx_s[(ty << 2) + r] = minidx[r];
            s = __fadd_rn(s, minval[r]);   // = ||z_r - c_idx||^2
        }
        lsum_s[ty] = s;
    }
    __syncthreads();

    if (tid == 0) {
        float s = 0.0f;
        #pragma unroll
        for (int i = 0; i < 16; i++) s = __fadd_rn(s, lsum_s[i]);
        g_partials[blockIdx.x] = s;
    }

    // ---- write indices (as float) ----
    if (tid < TM) {
        out[NROWS * DIM + 1 + rowBase + tid] = (float)ridx_s[tid];
    }

    // ---- write z_q = codebook[idx] (coalesced) ----
    #pragma unroll
    for (int i = 0; i < 16; i++) {
        int flat = i * NTHREADS + tid;
        int r = flat >> 6, c = flat & 63;
        out[(rowBase + r) * DIM + c] = codebook[ridx_s[r] * DIM + c];
    }
}

// ---------------------------------------------------------------------------
// Kernel 3: deterministic loss reduce.
// loss = mean + 0.25*mean, mean = sum(||z - z_q||^2) / (N*D)
// ---------------------------------------------------------------------------
__global__ void loss_kernel(float* __restrict__ out) {
    __shared__ float s[NBLOCKS];
    int tid = threadIdx.x;
    s[tid] = g_partials[tid];
    __syncthreads();
    for (int m = NBLOCKS / 2; m > 0; m >>= 1) {
        if (tid < m) s[tid] = __fadd_rn(s[tid], s[tid + m]);
        __syncthreads();
    }
    if (tid == 0) {
        float mean = s[0] / (float)(NROWS * DIM);   // /2^21: exact
        out[NROWS * DIM] = __fadd_rn(mean, __fmul_rn(0.25f, mean));
    }
}

extern "C" void kernel_launch(void* const* d_in, const int* in_sizes, int n_in,
                              void* d_out, int out_size) {
    const float* z        = (const float*)d_in[0];
    const float* codebook = (const float*)d_in[1];
    float* out = (float*)d_out;

    cnorm_kernel<<<KCODES / 64, 64>>>(codebook);
    vq_kernel<<<NBLOCKS, NTHREADS>>>(z, codebook, out);
    loss_kernel<<<1, NBLOCKS>>>(out);
}